// round 12
// baseline (speedup 1.0000x reference)
#include <cuda_runtime.h>

#define HD 20
#define G4 80
#define LN_EPS 1e-5f

// ---- lookup table over x in [XLO, XHI] ----
// Data is N(0,1); F is asymptotically constant (input LN is scale-invariant),
// so clamping at +-6.5 is safe. Calibrated interp err ~= 0.86*h^2 -> 1.3e-4.
#define TAB_N 1024                 // intervals
#define XLO (-6.5f)
#define XHI (6.5f)

#define BUILD_THREADS 64           // 16 points/block (4 threads/point) -> 65 blocks
#define INTERP_THREADS 256
#define INTERP_BLOCKS 296          // 2 per SM: halve staging, ILP covers latency
#define EPI 16                     // elements per thread per iteration

// table stored as adjacent pairs: g_pairs[i] = (F[i], F[i+1])
__device__ float2 g_pairs[TAB_N + 1];

// ---- fast-but-accurate transcendentals ----
__device__ __forceinline__ float ex2a(float x) {
    float r; asm("ex2.approx.f32 %0, %1;" : "=f"(r) : "f"(x)); return r;
}
__device__ __forceinline__ float rcpa(float x) {
    float r; asm("rcp.approx.f32 %0, %1;" : "=f"(r) : "f"(x)); return r;
}
__device__ __forceinline__ float sqrta(float x) {
    float r; asm("sqrt.approx.f32 %0, %1;" : "=f"(r) : "f"(x)); return r;
}
#define LOG2E 1.4426950408889634f
__device__ __forceinline__ float sigm(float x) {
    return rcpa(1.0f + ex2a(-LOG2E * x));
}
__device__ __forceinline__ float tanha(float x) {
    return fmaf(2.0f, rcpa(1.0f + ex2a(-2.0f * LOG2E * x)), -1.0f);
}

struct SW {
    float W1[HD], b1[HD], g1[HD], be1[HD];
    float Wih0[G4 * HD];
    float gi0[G4], bib0[G4];   // bib = bi + bh (hx=0 folds _ln(0)=bh)
    float go0[HD], bo0[HD];
    float Wih1[G4 * HD];
    float gi1[G4], bib1[G4];
    float go1[HD], bo1[HD];
    float Wout[HD];
    float bout;
};

__device__ __forceinline__ float grp4_sum(float v) {
    v += __shfl_xor_sync(0xffffffffu, v, 1, 4);
    v += __shfl_xor_sync(0xffffffffu, v, 2, 4);
    return v;
}

// One LSTM cell (hx=cx=0 entering), split across 4 threads (r = lane%4).
__device__ __forceinline__ void cell4(int r,
                                      const float* __restrict__ xin,
                                      const float* __restrict__ W,
                                      const float* __restrict__ gi,
                                      const float* __restrict__ bib,
                                      const float* __restrict__ go,
                                      const float* __restrict__ bo,
                                      float* __restrict__ hq)
{
    const int g0 = 5 * r;
    float ui[5], uf[5], uo[5], ug[5];
    float su = 0.0f, sq = 0.0f;
    #pragma unroll
    for (int j = 0; j < 5; j++) {
        int h = g0 + j;
        float a0 = 0.0f, a1 = 0.0f, a2 = 0.0f, a3 = 0.0f;
        #pragma unroll
        for (int k = 0; k < HD; k++) {
            float xk = xin[k];
            a0 = fmaf(xk, W[(h)      * HD + k], a0);
            a1 = fmaf(xk, W[(20 + h) * HD + k], a1);
            a2 = fmaf(xk, W[(40 + h) * HD + k], a2);
            a3 = fmaf(xk, W[(60 + h) * HD + k], a3);
        }
        ui[j] = a0; uf[j] = a1; uo[j] = a2; ug[j] = a3;
        su += a0 + a1 + a2 + a3;
        sq = fmaf(a0, a0, sq);
        sq = fmaf(a1, a1, sq);
        sq = fmaf(a2, a2, sq);
        sq = fmaf(a3, a3, sq);
    }
    su = grp4_sum(su);
    sq = grp4_sum(sq);

    float mu  = su * (1.0f / G4);
    float var = fmaf(-(float)G4, mu * mu, sq) * (1.0f / (G4 - 1));
    var = fmaxf(var, 0.0f);
    float sfac = rcpa(sqrta(var) + LN_EPS);

    float c[5];
    float suc = 0.0f;
    #pragma unroll
    for (int j = 0; j < 5; j++) {
        int h = g0 + j;
        float ai = fmaf((ui[j] - mu) * sfac, gi[h],      bib[h]);
        float ag = fmaf((ug[j] - mu) * sfac, gi[60 + h], bib[60 + h]);
        c[j] = sigm(ai) * tanha(ag);
        suc += c[j];
    }
    suc = grp4_sum(suc);
    float muc = suc * (1.0f / HD);

    float varc = 0.0f;
    #pragma unroll
    for (int j = 0; j < 5; j++) {
        float d = c[j] - muc;
        varc = fmaf(d, d, varc);
    }
    varc = grp4_sum(varc);
    varc *= (1.0f / (HD - 1));
    float sc = rcpa(sqrta(varc) + LN_EPS);

    #pragma unroll
    for (int j = 0; j < 5; j++) {
        int h = g0 + j;
        float ao = fmaf((uo[j] - mu) * sfac, gi[40 + h], bib[40 + h]);
        float lc = fmaf((c[j] - muc) * sc, go[h], bo[h]);
        hq[j] = sigm(ao) * tanha(lc);
    }
}

__device__ __forceinline__ void gather20(const float* __restrict__ hq,
                                         float* __restrict__ full)
{
    #pragma unroll
    for (int k = 0; k < HD; k++)
        full[k] = __shfl_sync(0xffffffffu, hq[k % 5], k / 5, 4);
}

__global__ void __launch_bounds__(BUILD_THREADS)
build_table_kernel(
            const float* __restrict__ W1,  const float* __restrict__ b1,
            const float* __restrict__ g1,  const float* __restrict__ be1,
            const float* __restrict__ Wih0, const float* __restrict__ gi0,
            const float* __restrict__ bi0, const float* __restrict__ bh0,
            const float* __restrict__ go0, const float* __restrict__ bo0,
            const float* __restrict__ Wih1, const float* __restrict__ gi1,
            const float* __restrict__ bi1, const float* __restrict__ bh1,
            const float* __restrict__ go1, const float* __restrict__ bo1,
            const float* __restrict__ Wout, const float* __restrict__ bout)
{
    __shared__ SW s;
    int t = threadIdx.x;

    {
        const float4* a = reinterpret_cast<const float4*>(Wih0);
        const float4* b = reinterpret_cast<const float4*>(Wih1);
        float4* sa = reinterpret_cast<float4*>(s.Wih0);
        float4* sb = reinterpret_cast<float4*>(s.Wih1);
        #pragma unroll
        for (int i = t; i < (G4 * HD) / 4; i += BUILD_THREADS) {
            sa[i] = a[i];
            sb[i] = b[i];
        }
    }
    for (int i = t; i < HD; i += BUILD_THREADS) {
        s.W1[i]  = W1[i];  s.b1[i]  = b1[i];
        s.g1[i]  = g1[i];  s.be1[i] = be1[i];
        s.go0[i] = go0[i]; s.bo0[i] = bo0[i];
        s.go1[i] = go1[i]; s.bo1[i] = bo1[i];
        s.Wout[i] = Wout[i];
    }
    for (int i = t; i < G4; i += BUILD_THREADS) {
        s.gi0[i]  = gi0[i];
        s.bib0[i] = bi0[i] + bh0[i];
        s.gi1[i]  = gi1[i];
        s.bib1[i] = bi1[i] + bh1[i];
    }
    if (t == 0) s.bout = bout[0];
    __syncthreads();

    int p = blockIdx.x * (BUILD_THREADS / 4) + (t >> 2);
    int r = t & 3;
    bool valid = (p <= TAB_N);
    if (p > TAB_N) p = TAB_N;      // converged clamp (keep all lanes for shfl)

    const float hstep = (XHI - XLO) / (float)TAB_N;
    float xv = XLO + (float)p * hstep;

    float v[HD];
    float sv = 0.0f;
    #pragma unroll
    for (int h = 0; h < HD; h++) {
        v[h] = fmaf(xv, s.W1[h], s.b1[h]);
        sv += v[h];
    }
    float mu = sv * (1.0f / HD);
    float var = 0.0f;
    #pragma unroll
    for (int h = 0; h < HD; h++) {
        float d = v[h] - mu;
        v[h] = d;
        var = fmaf(d, d, var);
    }
    var *= (1.0f / (HD - 1));
    float sfac = rcpa(sqrta(var) + LN_EPS);

    float xt[HD];
    #pragma unroll
    for (int h = 0; h < HD; h++)
        xt[h] = tanha(fmaf(v[h] * sfac, s.g1[h], s.be1[h]));

    float hq0[5];
    cell4(r, xt, s.Wih0, s.gi0, s.bib0, s.go0, s.bo0, hq0);
    float hx0[HD];
    gather20(hq0, hx0);

    float hq1[5];
    cell4(r, hx0, s.Wih1, s.gi1, s.bib1, s.go1, s.bo1, hq1);

    float acc = 0.0f;
    #pragma unroll
    for (int j = 0; j < 5; j++)
        acc = fmaf(hq1[j], s.Wout[5 * r + j], acc);
    acc = grp4_sum(acc);

    if (r == 0 && valid) {
        float val = acc + s.bout;
        if (p < TAB_N) g_pairs[p].x = val;
        if (p > 0)     g_pairs[p - 1].y = val;
    }
    __threadfence();
    __syncthreads();
#if __CUDA_ARCH__ >= 900
    cudaTriggerProgrammaticLaunchCompletion();
#endif
}

// Interp: 16 elems/thread/iter, software-pipelined x prefetch, smem gathers.
__global__ void __launch_bounds__(INTERP_THREADS)
interp_kernel(const float* __restrict__ x, float* __restrict__ out, int N)
{
    __shared__ float2 stab[TAB_N];   // 8 KB

    const int nchunk = N >> 4;       // 16-elem chunks (N=4M divisible by 16)
    const int stride = INTERP_BLOCKS * INTERP_THREADS;
    const float4* x4 = reinterpret_cast<const float4*>(x);
    float4* o4 = reinterpret_cast<float4*>(out);

    const int v0 = blockIdx.x * INTERP_THREADS + threadIdx.x;

    // prefetch iteration-0 x loads BEFORE depending on the build kernel
    float4 c0, c1, c2, c3;
    if (v0 < nchunk) {
        c0 = x4[4 * v0];
        c1 = x4[4 * v0 + 1];
        c2 = x4[4 * v0 + 2];
        c3 = x4[4 * v0 + 3];
    }

#if __CUDA_ARCH__ >= 900
    cudaGridDependencySynchronize();   // wait until build published the table
#endif

    {
        const float4* src = reinterpret_cast<const float4*>(g_pairs);
        float4* dst = reinterpret_cast<float4*>(stab);
        #pragma unroll
        for (int i = threadIdx.x; i < TAB_N / 2; i += INTERP_THREADS)
            dst[i] = src[i];
    }
    __syncthreads();

    const float inv_s  = 1.0f / (XHI - XLO);
    const float bias_s = -XLO * inv_s;
    const float SCALE  = (float)TAB_N - 0.002f;

    for (int v = v0; v < nchunk; v += stride) {
        // prefetch next iteration's x while current is processed
        int vn = v + stride;
        float4 n0, n1, n2, n3;
        if (vn < nchunk) {
            n0 = x4[4 * vn];
            n1 = x4[4 * vn + 1];
            n2 = x4[4 * vn + 2];
            n3 = x4[4 * vn + 3];
        }

        float xs[EPI] = {c0.x, c0.y, c0.z, c0.w,  c1.x, c1.y, c1.z, c1.w,
                         c2.x, c2.y, c2.z, c2.w,  c3.x, c3.y, c3.z, c3.w};

        float f[EPI];
        float2 tp[EPI];
        #pragma unroll
        for (int j = 0; j < EPI; j++) {
            float u = __saturatef(fmaf(xs[j], inv_s, bias_s)) * SCALE;
            int i = (int)u;
            f[j]  = u - (float)i;
            tp[j] = stab[i];
        }
        float rs[EPI];
        #pragma unroll
        for (int j = 0; j < EPI; j++)
            rs[j] = fmaf(f[j], tp[j].y - tp[j].x, tp[j].x);

        o4[4 * v]     = make_float4(rs[0],  rs[1],  rs[2],  rs[3]);
        o4[4 * v + 1] = make_float4(rs[4],  rs[5],  rs[6],  rs[7]);
        o4[4 * v + 2] = make_float4(rs[8],  rs[9],  rs[10], rs[11]);
        o4[4 * v + 3] = make_float4(rs[12], rs[13], rs[14], rs[15]);

        c0 = n0; c1 = n1; c2 = n2; c3 = n3;
    }

    // scalar tail (N not divisible by 16 — not hit for N=4M, kept for safety)
    int ntail = N & 15;
    if (ntail && blockIdx.x == 0 && threadIdx.x < ntail) {
        int n = (N & ~15) + threadIdx.x;
        float u = __saturatef(fmaf(x[n], inv_s, bias_s)) * SCALE;
        int i = (int)u;
        float f = u - (float)i;
        float2 tv = stab[i];
        out[n] = fmaf(f, tv.y - tv.x, tv.x);
    }
}

extern "C" void kernel_launch(void* const* d_in, const int* in_sizes, int n_in,
                              void* d_out, int out_size)
{
    const float* x    = (const float*)d_in[0];
    const float* W1   = (const float*)d_in[1];
    const float* b1   = (const float*)d_in[2];
    const float* g1   = (const float*)d_in[3];
    const float* be1  = (const float*)d_in[4];
    const float* Wih0 = (const float*)d_in[5];
    const float* gi0  = (const float*)d_in[7];
    const float* bi0  = (const float*)d_in[8];
    const float* bh0  = (const float*)d_in[10];
    const float* go0  = (const float*)d_in[11];
    const float* bo0  = (const float*)d_in[12];
    const float* Wih1 = (const float*)d_in[13];
    const float* gi1  = (const float*)d_in[15];
    const float* bi1  = (const float*)d_in[16];
    const float* bh1  = (const float*)d_in[18];
    const float* go1  = (const float*)d_in[19];
    const float* bo1  = (const float*)d_in[20];
    const float* Wout = (const float*)d_in[21];
    const float* boutp= (const float*)d_in[22];

    int N = in_sizes[0];

    int pts = TAB_N + 1;
    int ppb = BUILD_THREADS / 4;              // 16 points per block
    int tab_blocks = (pts + ppb - 1) / ppb;   // 65
    build_table_kernel<<<tab_blocks, BUILD_THREADS>>>(
        W1, b1, g1, be1,
        Wih0, gi0, bi0, bh0, go0, bo0,
        Wih1, gi1, bi1, bh1, go1, bo1,
        Wout, boutp);

    // PDL launch: interp may start while build drains; it prefetches x and
    // then grid-dependency-syncs before touching the table.
    cudaLaunchConfig_t cfg = {};
    cfg.gridDim  = dim3(INTERP_BLOCKS, 1, 1);
    cfg.blockDim = dim3(INTERP_THREADS, 1, 1);
    cfg.dynamicSmemBytes = 0;
    cudaLaunchAttribute attrs[1];
    attrs[0].id = cudaLaunchAttributeProgrammaticStreamSerialization;
    attrs[0].val.programmaticStreamSerializationAllowed = 1;
    cfg.attrs = attrs;
    cfg.numAttrs = 1;
    cudaError_t err = cudaLaunchKernelEx(&cfg, interp_kernel,
                                         x, (float*)d_out, N);
    if (err != cudaSuccess) {
        interp_kernel<<<INTERP_BLOCKS, INTERP_THREADS>>>(x, (float*)d_out, N);
    }
}

// round 13
// speedup vs baseline: 1.3502x; 1.3502x over previous
#include <cuda_runtime.h>

#define HD 20
#define G4 80
#define LN_EPS 1e-5f

// ---- lookup table over x in [XLO, XHI] ----
// Data is N(0,1); F is asymptotically constant (input LN is scale-invariant),
// so clamping at +-6.5 is safe. Calibrated interp err ~= 0.86*h^2 -> 1.3e-4.
#define TAB_N 1024                 // intervals
#define XLO (-6.5f)
#define XHI (6.5f)

#define BUILD_THREADS 64           // 16 points/block (4 threads/point) -> 65 blocks
#define INTERP_THREADS 256
#define INTERP_BLOCKS 592          // 4 per SM (proven best)

// table stored as adjacent pairs: g_pairs[i] = (F[i], F[i+1])
__device__ float2 g_pairs[TAB_N + 1];

// ---- fast-but-accurate transcendentals ----
__device__ __forceinline__ float ex2a(float x) {
    float r; asm("ex2.approx.f32 %0, %1;" : "=f"(r) : "f"(x)); return r;
}
__device__ __forceinline__ float rcpa(float x) {
    float r; asm("rcp.approx.f32 %0, %1;" : "=f"(r) : "f"(x)); return r;
}
__device__ __forceinline__ float sqrta(float x) {
    float r; asm("sqrt.approx.f32 %0, %1;" : "=f"(r) : "f"(x)); return r;
}
#define LOG2E 1.4426950408889634f
__device__ __forceinline__ float sigm(float x) {
    return rcpa(1.0f + ex2a(-LOG2E * x));
}
__device__ __forceinline__ float tanha(float x) {
    return fmaf(2.0f, rcpa(1.0f + ex2a(-2.0f * LOG2E * x)), -1.0f);
}

struct SW {
    float W1[HD], b1[HD], g1[HD], be1[HD];
    float Wih0[G4 * HD];
    float gi0[G4], bib0[G4];   // bib = bi + bh (hx=0 folds _ln(0)=bh)
    float go0[HD], bo0[HD];
    float Wih1[G4 * HD];
    float gi1[G4], bib1[G4];
    float go1[HD], bo1[HD];
    float Wout[HD];
    float bout;
};

__device__ __forceinline__ float grp4_sum(float v) {
    v += __shfl_xor_sync(0xffffffffu, v, 1, 4);
    v += __shfl_xor_sync(0xffffffffu, v, 2, 4);
    return v;
}

// One LSTM cell (hx=cx=0 entering), split across 4 threads (r = lane%4).
__device__ __forceinline__ void cell4(int r,
                                      const float* __restrict__ xin,
                                      const float* __restrict__ W,
                                      const float* __restrict__ gi,
                                      const float* __restrict__ bib,
                                      const float* __restrict__ go,
                                      const float* __restrict__ bo,
                                      float* __restrict__ hq)
{
    const int g0 = 5 * r;
    float ui[5], uf[5], uo[5], ug[5];
    float su = 0.0f, sq = 0.0f;
    #pragma unroll
    for (int j = 0; j < 5; j++) {
        int h = g0 + j;
        float a0 = 0.0f, a1 = 0.0f, a2 = 0.0f, a3 = 0.0f;
        #pragma unroll
        for (int k = 0; k < HD; k++) {
            float xk = xin[k];
            a0 = fmaf(xk, W[(h)      * HD + k], a0);
            a1 = fmaf(xk, W[(20 + h) * HD + k], a1);
            a2 = fmaf(xk, W[(40 + h) * HD + k], a2);
            a3 = fmaf(xk, W[(60 + h) * HD + k], a3);
        }
        ui[j] = a0; uf[j] = a1; uo[j] = a2; ug[j] = a3;
        su += a0 + a1 + a2 + a3;
        sq = fmaf(a0, a0, sq);
        sq = fmaf(a1, a1, sq);
        sq = fmaf(a2, a2, sq);
        sq = fmaf(a3, a3, sq);
    }
    su = grp4_sum(su);
    sq = grp4_sum(sq);

    float mu  = su * (1.0f / G4);
    float var = fmaf(-(float)G4, mu * mu, sq) * (1.0f / (G4 - 1));
    var = fmaxf(var, 0.0f);
    float sfac = rcpa(sqrta(var) + LN_EPS);

    float c[5];
    float suc = 0.0f;
    #pragma unroll
    for (int j = 0; j < 5; j++) {
        int h = g0 + j;
        float ai = fmaf((ui[j] - mu) * sfac, gi[h],      bib[h]);
        float ag = fmaf((ug[j] - mu) * sfac, gi[60 + h], bib[60 + h]);
        c[j] = sigm(ai) * tanha(ag);
        suc += c[j];
    }
    suc = grp4_sum(suc);
    float muc = suc * (1.0f / HD);

    float varc = 0.0f;
    #pragma unroll
    for (int j = 0; j < 5; j++) {
        float d = c[j] - muc;
        varc = fmaf(d, d, varc);
    }
    varc = grp4_sum(varc);
    varc *= (1.0f / (HD - 1));
    float sc = rcpa(sqrta(varc) + LN_EPS);

    #pragma unroll
    for (int j = 0; j < 5; j++) {
        int h = g0 + j;
        float ao = fmaf((uo[j] - mu) * sfac, gi[40 + h], bib[40 + h]);
        float lc = fmaf((c[j] - muc) * sc, go[h], bo[h]);
        hq[j] = sigm(ao) * tanha(lc);
    }
}

__device__ __forceinline__ void gather20(const float* __restrict__ hq,
                                         float* __restrict__ full)
{
    #pragma unroll
    for (int k = 0; k < HD; k++)
        full[k] = __shfl_sync(0xffffffffu, hq[k % 5], k / 5, 4);
}

__global__ void __launch_bounds__(BUILD_THREADS)
build_table_kernel(
            const float* __restrict__ W1,  const float* __restrict__ b1,
            const float* __restrict__ g1,  const float* __restrict__ be1,
            const float* __restrict__ Wih0, const float* __restrict__ gi0,
            const float* __restrict__ bi0, const float* __restrict__ bh0,
            const float* __restrict__ go0, const float* __restrict__ bo0,
            const float* __restrict__ Wih1, const float* __restrict__ gi1,
            const float* __restrict__ bi1, const float* __restrict__ bh1,
            const float* __restrict__ go1, const float* __restrict__ bo1,
            const float* __restrict__ Wout, const float* __restrict__ bout)
{
    __shared__ SW s;
    int t = threadIdx.x;

    {
        const float4* a = reinterpret_cast<const float4*>(Wih0);
        const float4* b = reinterpret_cast<const float4*>(Wih1);
        float4* sa = reinterpret_cast<float4*>(s.Wih0);
        float4* sb = reinterpret_cast<float4*>(s.Wih1);
        #pragma unroll
        for (int i = t; i < (G4 * HD) / 4; i += BUILD_THREADS) {
            sa[i] = a[i];
            sb[i] = b[i];
        }
    }
    for (int i = t; i < HD; i += BUILD_THREADS) {
        s.W1[i]  = W1[i];  s.b1[i]  = b1[i];
        s.g1[i]  = g1[i];  s.be1[i] = be1[i];
        s.go0[i] = go0[i]; s.bo0[i] = bo0[i];
        s.go1[i] = go1[i]; s.bo1[i] = bo1[i];
        s.Wout[i] = Wout[i];
    }
    for (int i = t; i < G4; i += BUILD_THREADS) {
        s.gi0[i]  = gi0[i];
        s.bib0[i] = bi0[i] + bh0[i];
        s.gi1[i]  = gi1[i];
        s.bib1[i] = bi1[i] + bh1[i];
    }
    if (t == 0) s.bout = bout[0];
    __syncthreads();

    int p = blockIdx.x * (BUILD_THREADS / 4) + (t >> 2);
    int r = t & 3;
    bool valid = (p <= TAB_N);
    if (p > TAB_N) p = TAB_N;      // converged clamp (keep all lanes for shfl)

    const float hstep = (XHI - XLO) / (float)TAB_N;
    float xv = XLO + (float)p * hstep;

    float v[HD];
    float sv = 0.0f;
    #pragma unroll
    for (int h = 0; h < HD; h++) {
        v[h] = fmaf(xv, s.W1[h], s.b1[h]);
        sv += v[h];
    }
    float mu = sv * (1.0f / HD);
    float var = 0.0f;
    #pragma unroll
    for (int h = 0; h < HD; h++) {
        float d = v[h] - mu;
        v[h] = d;
        var = fmaf(d, d, var);
    }
    var *= (1.0f / (HD - 1));
    float sfac = rcpa(sqrta(var) + LN_EPS);

    float xt[HD];
    #pragma unroll
    for (int h = 0; h < HD; h++)
        xt[h] = tanha(fmaf(v[h] * sfac, s.g1[h], s.be1[h]));

    float hq0[5];
    cell4(r, xt, s.Wih0, s.gi0, s.bib0, s.go0, s.bo0, hq0);
    float hx0[HD];
    gather20(hq0, hx0);

    float hq1[5];
    cell4(r, hx0, s.Wih1, s.gi1, s.bib1, s.go1, s.bo1, hq1);

    float acc = 0.0f;
    #pragma unroll
    for (int j = 0; j < 5; j++)
        acc = fmaf(hq1[j], s.Wout[5 * r + j], acc);
    acc = grp4_sum(acc);

    if (r == 0 && valid) {
        float val = acc + s.bout;
        if (p < TAB_N) g_pairs[p].x = val;
        if (p > 0)     g_pairs[p - 1].y = val;
    }
    __threadfence();
    __syncthreads();
#if __CUDA_ARCH__ >= 900
    cudaTriggerProgrammaticLaunchCompletion();
#endif
}

// Interp: proven 8-EPI / 592-block loop + software-pipelined x prefetch.
__global__ void __launch_bounds__(INTERP_THREADS)
interp_kernel(const float* __restrict__ x, float* __restrict__ out, int N)
{
    __shared__ float2 stab[TAB_N];   // 8 KB

    const int nvec = N >> 3;   // 8 elems per iteration
    const int stride = INTERP_BLOCKS * INTERP_THREADS;
    const float4* x4 = reinterpret_cast<const float4*>(x);
    float4* o4 = reinterpret_cast<float4*>(out);

    const int v0 = blockIdx.x * INTERP_THREADS + threadIdx.x;

    // prefetch iteration-0 x loads BEFORE depending on the build kernel
    float4 xa, xb;
    if (v0 < nvec) {
        xa = x4[2 * v0];
        xb = x4[2 * v0 + 1];
    }

#if __CUDA_ARCH__ >= 900
    cudaGridDependencySynchronize();   // wait until build published the table
#endif

    {
        const float4* src = reinterpret_cast<const float4*>(g_pairs);
        float4* dst = reinterpret_cast<float4*>(stab);
        #pragma unroll
        for (int i = threadIdx.x; i < TAB_N / 2; i += INTERP_THREADS)
            dst[i] = src[i];
    }
    __syncthreads();

    const float inv_s  = 1.0f / (XHI - XLO);
    const float bias_s = -XLO * inv_s;
    const float SCALE  = (float)TAB_N - 0.002f;

    for (int v = v0; v < nvec; v += stride) {
        // prefetch next iteration's x while this one computes
        int vn = v + stride;
        float4 na, nb;
        if (vn < nvec) {
            na = x4[2 * vn];
            nb = x4[2 * vn + 1];
        }

        float xs[8] = {xa.x, xa.y, xa.z, xa.w, xb.x, xb.y, xb.z, xb.w};

        float f[8];
        float2 tp[8];
        #pragma unroll
        for (int j = 0; j < 8; j++) {
            float u = __saturatef(fmaf(xs[j], inv_s, bias_s)) * SCALE;
            int i = (int)u;
            f[j]  = u - (float)i;
            tp[j] = stab[i];
        }
        float rs[8];
        #pragma unroll
        for (int j = 0; j < 8; j++)
            rs[j] = fmaf(f[j], tp[j].y - tp[j].x, tp[j].x);

        o4[2 * v]     = make_float4(rs[0], rs[1], rs[2], rs[3]);
        o4[2 * v + 1] = make_float4(rs[4], rs[5], rs[6], rs[7]);

        xa = na; xb = nb;
    }

    int ntail = N & 7;
    if (ntail && blockIdx.x == 0 && threadIdx.x < ntail) {
        int n = (N & ~7) + threadIdx.x;
        float u = __saturatef(fmaf(x[n], inv_s, bias_s)) * SCALE;
        int i = (int)u;
        float f = u - (float)i;
        float2 tv = stab[i];
        out[n] = fmaf(f, tv.y - tv.x, tv.x);
    }
}

extern "C" void kernel_launch(void* const* d_in, const int* in_sizes, int n_in,
                              void* d_out, int out_size)
{
    const float* x    = (const float*)d_in[0];
    const float* W1   = (const float*)d_in[1];
    const float* b1   = (const float*)d_in[2];
    const float* g1   = (const float*)d_in[3];
    const float* be1  = (const float*)d_in[4];
    const float* Wih0 = (const float*)d_in[5];
    const float* gi0  = (const float*)d_in[7];
    const float* bi0  = (const float*)d_in[8];
    const float* bh0  = (const float*)d_in[10];
    const float* go0  = (const float*)d_in[11];
    const float* bo0  = (const float*)d_in[12];
    const float* Wih1 = (const float*)d_in[13];
    const float* gi1  = (const float*)d_in[15];
    const float* bi1  = (const float*)d_in[16];
    const float* bh1  = (const float*)d_in[18];
    const float* go1  = (const float*)d_in[19];
    const float* bo1  = (const float*)d_in[20];
    const float* Wout = (const float*)d_in[21];
    const float* boutp= (const float*)d_in[22];

    int N = in_sizes[0];

    int pts = TAB_N + 1;
    int ppb = BUILD_THREADS / 4;              // 16 points per block
    int tab_blocks = (pts + ppb - 1) / ppb;   // 65
    build_table_kernel<<<tab_blocks, BUILD_THREADS>>>(
        W1, b1, g1, be1,
        Wih0, gi0, bi0, bh0, go0, bo0,
        Wih1, gi1, bi1, bh1, go1, bo1,
        Wout, boutp);

    // PDL launch: interp starts while build drains; prefetches x, then
    // grid-dependency-syncs before touching the table.
    cudaLaunchConfig_t cfg = {};
    cfg.gridDim  = dim3(INTERP_BLOCKS, 1, 1);
    cfg.blockDim = dim3(INTERP_THREADS, 1, 1);
    cfg.dynamicSmemBytes = 0;
    cudaLaunchAttribute attrs[1];
    attrs[0].id = cudaLaunchAttributeProgrammaticStreamSerialization;
    attrs[0].val.programmaticStreamSerializationAllowed = 1;
    cfg.attrs = attrs;
    cfg.numAttrs = 1;
    cudaError_t err = cudaLaunchKernelEx(&cfg, interp_kernel,
                                         x, (float*)d_out, N);
    if (err != cudaSuccess) {
        interp_kernel<<<INTERP_BLOCKS, INTERP_THREADS>>>(x, (float*)d_out, N);
    }
}

// round 14
// speedup vs baseline: 1.6243x; 1.2030x over previous
#include <cuda_runtime.h>

#define HD 20
#define G4 80
#define LN_EPS 1e-5f

// ---- lookup table over x in [XLO, XHI] ----
// Data is N(0,1); F is asymptotically constant (input LN is scale-invariant),
// so clamping at +-6.5 is safe. Calibrated interp err ~= 0.86*h^2 -> 1.3e-4.
#define TAB_N 1024                 // intervals (index fits 0x3FF mask)
#define XLO (-6.5f)
#define XHI (6.5f)

#define BUILD_THREADS 64           // 16 points/block (4 threads/point) -> 65 blocks
#define INTERP_THREADS 256
#define INTERP_BLOCKS 592          // 4 per SM (proven best)

#define MAGIC 12582912.0f          // 1.5 * 2^23 ; bits = 0x4B400000

// table stored as adjacent pairs: g_pairs[i] = (F[i], F[i+1])
__device__ float2 g_pairs[TAB_N + 1];

// ---- fast-but-accurate transcendentals ----
__device__ __forceinline__ float ex2a(float x) {
    float r; asm("ex2.approx.f32 %0, %1;" : "=f"(r) : "f"(x)); return r;
}
__device__ __forceinline__ float rcpa(float x) {
    float r; asm("rcp.approx.f32 %0, %1;" : "=f"(r) : "f"(x)); return r;
}
__device__ __forceinline__ float sqrta(float x) {
    float r; asm("sqrt.approx.f32 %0, %1;" : "=f"(r) : "f"(x)); return r;
}
#define LOG2E 1.4426950408889634f
__device__ __forceinline__ float sigm(float x) {
    return rcpa(1.0f + ex2a(-LOG2E * x));
}
__device__ __forceinline__ float tanha(float x) {
    return fmaf(2.0f, rcpa(1.0f + ex2a(-2.0f * LOG2E * x)), -1.0f);
}

struct SW {
    float W1[HD], b1[HD], g1[HD], be1[HD];
    float Wih0[G4 * HD];
    float gi0[G4], bib0[G4];   // bib = bi + bh (hx=0 folds _ln(0)=bh)
    float go0[HD], bo0[HD];
    float Wih1[G4 * HD];
    float gi1[G4], bib1[G4];
    float go1[HD], bo1[HD];
    float Wout[HD];
    float bout;
};

__device__ __forceinline__ float grp4_sum(float v) {
    v += __shfl_xor_sync(0xffffffffu, v, 1, 4);
    v += __shfl_xor_sync(0xffffffffu, v, 2, 4);
    return v;
}

// One LSTM cell (hx=cx=0 entering), split across 4 threads (r = lane%4).
__device__ __forceinline__ void cell4(int r,
                                      const float* __restrict__ xin,
                                      const float* __restrict__ W,
                                      const float* __restrict__ gi,
                                      const float* __restrict__ bib,
                                      const float* __restrict__ go,
                                      const float* __restrict__ bo,
                                      float* __restrict__ hq)
{
    const int g0 = 5 * r;
    float ui[5], uf[5], uo[5], ug[5];
    float su = 0.0f, sq = 0.0f;
    #pragma unroll
    for (int j = 0; j < 5; j++) {
        int h = g0 + j;
        float a0 = 0.0f, a1 = 0.0f, a2 = 0.0f, a3 = 0.0f;
        #pragma unroll
        for (int k = 0; k < HD; k++) {
            float xk = xin[k];
            a0 = fmaf(xk, W[(h)      * HD + k], a0);
            a1 = fmaf(xk, W[(20 + h) * HD + k], a1);
            a2 = fmaf(xk, W[(40 + h) * HD + k], a2);
            a3 = fmaf(xk, W[(60 + h) * HD + k], a3);
        }
        ui[j] = a0; uf[j] = a1; uo[j] = a2; ug[j] = a3;
        su += a0 + a1 + a2 + a3;
        sq = fmaf(a0, a0, sq);
        sq = fmaf(a1, a1, sq);
        sq = fmaf(a2, a2, sq);
        sq = fmaf(a3, a3, sq);
    }
    su = grp4_sum(su);
    sq = grp4_sum(sq);

    float mu  = su * (1.0f / G4);
    float var = fmaf(-(float)G4, mu * mu, sq) * (1.0f / (G4 - 1));
    var = fmaxf(var, 0.0f);
    float sfac = rcpa(sqrta(var) + LN_EPS);

    float c[5];
    float suc = 0.0f;
    #pragma unroll
    for (int j = 0; j < 5; j++) {
        int h = g0 + j;
        float ai = fmaf((ui[j] - mu) * sfac, gi[h],      bib[h]);
        float ag = fmaf((ug[j] - mu) * sfac, gi[60 + h], bib[60 + h]);
        c[j] = sigm(ai) * tanha(ag);
        suc += c[j];
    }
    suc = grp4_sum(suc);
    float muc = suc * (1.0f / HD);

    float varc = 0.0f;
    #pragma unroll
    for (int j = 0; j < 5; j++) {
        float d = c[j] - muc;
        varc = fmaf(d, d, varc);
    }
    varc = grp4_sum(varc);
    varc *= (1.0f / (HD - 1));
    float sc = rcpa(sqrta(varc) + LN_EPS);

    #pragma unroll
    for (int j = 0; j < 5; j++) {
        int h = g0 + j;
        float ao = fmaf((uo[j] - mu) * sfac, gi[40 + h], bib[40 + h]);
        float lc = fmaf((c[j] - muc) * sc, go[h], bo[h]);
        hq[j] = sigm(ao) * tanha(lc);
    }
}

__device__ __forceinline__ void gather20(const float* __restrict__ hq,
                                         float* __restrict__ full)
{
    #pragma unroll
    for (int k = 0; k < HD; k++)
        full[k] = __shfl_sync(0xffffffffu, hq[k % 5], k / 5, 4);
}

__global__ void __launch_bounds__(BUILD_THREADS)
build_table_kernel(
            const float* __restrict__ W1,  const float* __restrict__ b1,
            const float* __restrict__ g1,  const float* __restrict__ be1,
            const float* __restrict__ Wih0, const float* __restrict__ gi0,
            const float* __restrict__ bi0, const float* __restrict__ bh0,
            const float* __restrict__ go0, const float* __restrict__ bo0,
            const float* __restrict__ Wih1, const float* __restrict__ gi1,
            const float* __restrict__ bi1, const float* __restrict__ bh1,
            const float* __restrict__ go1, const float* __restrict__ bo1,
            const float* __restrict__ Wout, const float* __restrict__ bout)
{
    __shared__ SW s;
    int t = threadIdx.x;

    {
        const float4* a = reinterpret_cast<const float4*>(Wih0);
        const float4* b = reinterpret_cast<const float4*>(Wih1);
        float4* sa = reinterpret_cast<float4*>(s.Wih0);
        float4* sb = reinterpret_cast<float4*>(s.Wih1);
        #pragma unroll
        for (int i = t; i < (G4 * HD) / 4; i += BUILD_THREADS) {
            sa[i] = a[i];
            sb[i] = b[i];
        }
    }
    for (int i = t; i < HD; i += BUILD_THREADS) {
        s.W1[i]  = W1[i];  s.b1[i]  = b1[i];
        s.g1[i]  = g1[i];  s.be1[i] = be1[i];
        s.go0[i] = go0[i]; s.bo0[i] = bo0[i];
        s.go1[i] = go1[i]; s.bo1[i] = bo1[i];
        s.Wout[i] = Wout[i];
    }
    for (int i = t; i < G4; i += BUILD_THREADS) {
        s.gi0[i]  = gi0[i];
        s.bib0[i] = bi0[i] + bh0[i];
        s.gi1[i]  = gi1[i];
        s.bib1[i] = bi1[i] + bh1[i];
    }
    if (t == 0) s.bout = bout[0];
    __syncthreads();

    int p = blockIdx.x * (BUILD_THREADS / 4) + (t >> 2);
    int r = t & 3;
    bool valid = (p <= TAB_N);
    if (p > TAB_N) p = TAB_N;      // converged clamp (keep all lanes for shfl)

    const float hstep = (XHI - XLO) / (float)TAB_N;
    float xv = XLO + (float)p * hstep;

    float v[HD];
    float sv = 0.0f;
    #pragma unroll
    for (int h = 0; h < HD; h++) {
        v[h] = fmaf(xv, s.W1[h], s.b1[h]);
        sv += v[h];
    }
    float mu = sv * (1.0f / HD);
    float var = 0.0f;
    #pragma unroll
    for (int h = 0; h < HD; h++) {
        float d = v[h] - mu;
        v[h] = d;
        var = fmaf(d, d, var);
    }
    var *= (1.0f / (HD - 1));
    float sfac = rcpa(sqrta(var) + LN_EPS);

    float xt[HD];
    #pragma unroll
    for (int h = 0; h < HD; h++)
        xt[h] = tanha(fmaf(v[h] * sfac, s.g1[h], s.be1[h]));

    float hq0[5];
    cell4(r, xt, s.Wih0, s.gi0, s.bib0, s.go0, s.bo0, hq0);
    float hx0[HD];
    gather20(hq0, hx0);

    float hq1[5];
    cell4(r, hx0, s.Wih1, s.gi1, s.bib1, s.go1, s.bo1, hq1);

    float acc = 0.0f;
    #pragma unroll
    for (int j = 0; j < 5; j++)
        acc = fmaf(hq1[j], s.Wout[5 * r + j], acc);
    acc = grp4_sum(acc);

    if (r == 0 && valid) {
        float val = acc + s.bout;
        if (p < TAB_N) g_pairs[p].x = val;
        if (p > 0)     g_pairs[p - 1].y = val;
    }
    __threadfence();
    __syncthreads();
#if __CUDA_ARCH__ >= 900
    cudaTriggerProgrammaticLaunchCompletion();
#endif
}

// Interp: proven 8-EPI / 592-block / 32-reg loop.
//  - pre-sync prefetch.global.L2 warms the x stream while build runs (PDL)
//  - magic-number floor removes F2I/I2F from the index path
__global__ void __launch_bounds__(INTERP_THREADS)
interp_kernel(const float* __restrict__ x, float* __restrict__ out, int N)
{
    __shared__ float2 stab[TAB_N];   // 8 KB

    const int nvec = N >> 3;   // 8 elems per iteration
    const int stride = INTERP_BLOCKS * INTERP_THREADS;
    const float4* x4 = reinterpret_cast<const float4*>(x);
    float4* o4 = reinterpret_cast<float4*>(out);

    const int v0 = blockIdx.x * INTERP_THREADS + threadIdx.x;

    // ---- pre-sync: warm L2 with this thread's x sectors (fire-and-forget).
    // x4[2v] and x4[2v+1] share one 32B sector -> 1 prefetch per iteration.
    for (int v = v0; v < nvec; v += stride)
        asm volatile("prefetch.global.L2 [%0];" :: "l"(x4 + 2 * v));

#if __CUDA_ARCH__ >= 900
    cudaGridDependencySynchronize();   // wait until build published the table
#endif

    {
        const float4* src = reinterpret_cast<const float4*>(g_pairs);
        float4* dst = reinterpret_cast<float4*>(stab);
        #pragma unroll
        for (int i = threadIdx.x; i < TAB_N / 2; i += INTERP_THREADS)
            dst[i] = src[i];
    }
    __syncthreads();

    const float inv_s  = 1.0f / (XHI - XLO);
    const float bias_s = -XLO * inv_s;
    const float SCALE  = (float)TAB_N - 0.002f;

    for (int v = v0; v < nvec; v += stride) {
        float4 xa = x4[2 * v];
        float4 xb = x4[2 * v + 1];
        float xs[8] = {xa.x, xa.y, xa.z, xa.w, xb.x, xb.y, xb.z, xb.w};

        float f[8];
        float2 tp[8];
        #pragma unroll
        for (int j = 0; j < 8; j++) {
            float u  = __saturatef(fmaf(xs[j], inv_s, bias_s)) * SCALE;
            float t  = (u - 0.5f) + MAGIC;          // round-to-nearest = floor(u)
            int   ib = __float_as_int(t) & 0x3FF;   // index in [0, 1023]
            float fi = t - MAGIC;                   // floor(u) as float
            f[j]  = u - fi;                         // frac in [0,1] (1.0 at ties: exact node)
            tp[j] = stab[ib];
        }
        float rs[8];
        #pragma unroll
        for (int j = 0; j < 8; j++)
            rs[j] = fmaf(f[j], tp[j].y - tp[j].x, tp[j].x);

        o4[2 * v]     = make_float4(rs[0], rs[1], rs[2], rs[3]);
        o4[2 * v + 1] = make_float4(rs[4], rs[5], rs[6], rs[7]);
    }

    int ntail = N & 7;
    if (ntail && blockIdx.x == 0 && threadIdx.x < ntail) {
        int n = (N & ~7) + threadIdx.x;
        float u  = __saturatef(fmaf(x[n], inv_s, bias_s)) * SCALE;
        float t  = (u - 0.5f) + MAGIC;
        int   ib = __float_as_int(t) & 0x3FF;
        float fi = t - MAGIC;
        float f  = u - fi;
        float2 tv = stab[ib];
        out[n] = fmaf(f, tv.y - tv.x, tv.x);
    }
}

extern "C" void kernel_launch(void* const* d_in, const int* in_sizes, int n_in,
                              void* d_out, int out_size)
{
    const float* x    = (const float*)d_in[0];
    const float* W1   = (const float*)d_in[1];
    const float* b1   = (const float*)d_in[2];
    const float* g1   = (const float*)d_in[3];
    const float* be1  = (const float*)d_in[4];
    const float* Wih0 = (const float*)d_in[5];
    const float* gi0  = (const float*)d_in[7];
    const float* bi0  = (const float*)d_in[8];
    const float* bh0  = (const float*)d_in[10];
    const float* go0  = (const float*)d_in[11];
    const float* bo0  = (const float*)d_in[12];
    const float* Wih1 = (const float*)d_in[13];
    const float* gi1  = (const float*)d_in[15];
    const float* bi1  = (const float*)d_in[16];
    const float* bh1  = (const float*)d_in[18];
    const float* go1  = (const float*)d_in[19];
    const float* bo1  = (const float*)d_in[20];
    const float* Wout = (const float*)d_in[21];
    const float* boutp= (const float*)d_in[22];

    int N = in_sizes[0];

    int pts = TAB_N + 1;
    int ppb = BUILD_THREADS / 4;              // 16 points per block
    int tab_blocks = (pts + ppb - 1) / ppb;   // 65
    build_table_kernel<<<tab_blocks, BUILD_THREADS>>>(
        W1, b1, g1, be1,
        Wih0, gi0, bi0, bh0, go0, bo0,
        Wih1, gi1, bi1, bh1, go1, bo1,
        Wout, boutp);

    // PDL launch: interp starts while build drains; prefetches x into L2,
    // then grid-dependency-syncs before touching the table.
    cudaLaunchConfig_t cfg = {};
    cfg.gridDim  = dim3(INTERP_BLOCKS, 1, 1);
    cfg.blockDim = dim3(INTERP_THREADS, 1, 1);
    cfg.dynamicSmemBytes = 0;
    cudaLaunchAttribute attrs[1];
    attrs[0].id = cudaLaunchAttributeProgrammaticStreamSerialization;
    attrs[0].val.programmaticStreamSerializationAllowed = 1;
    cfg.attrs = attrs;
    cfg.numAttrs = 1;
    cudaError_t err = cudaLaunchKernelEx(&cfg, interp_kernel,
                                         x, (float*)d_out, N);
    if (err != cudaSuccess) {
        interp_kernel<<<INTERP_BLOCKS, INTERP_THREADS>>>(x, (float*)d_out, N);
    }
}